// round 11
// baseline (speedup 1.0000x reference)
#include <cuda_runtime.h>
#include <math.h>
#include <stdint.h>

// KoLeoLoss: x [8192, 1024] fp32 -> scalar loss
//   xn = x / max(||x||, 1e-8)
//   I[r] = argmax_{c != r} (xn[r] . xn[c])
//   dist[r] = || xn[r] - xn[I[r]] + 1e-8 ||_2
//   loss = -mean(log(dist + 1e-8))
//
// Pipeline (2 launches):
//   K1 (fused): first 128 CTAs quantize 64 rows each (warp-per-row norms +
//       s8 x512) and release per-128-row-block flags; all 2080 CTAs spin on
//       their tile's two block flags, then run int8 mma.m16n8k32 (IMMA,
//       1024 MAC/cyc/SM) on upper-triangular 128x128 tiles; 2-stage ring,
//       2 CTAs/SM; dual-sided reduction -> per-(row, col-block) winners.
//   K2: per row, top-2 of 64 block winners by s32 score; fp32 rescore
//       (on-the-fly normalize from raw x) -> log -> g_loss; last block
//       writes the scalar and clears flags/counters for the next replay.

#define NB 8192
#define ND 1024
#define EPSF 1e-8f
#define QSCALE 512.0f

#define BM 128
#define BN 128
#define BKB 128                      // K-bytes per chunk (128 s8)
#define NCH (ND / BKB)               // 8
#define NST 2
#define NTB (NB / BM)                // 64
#define NTRI (NTB * (NTB + 1) / 2)   // 2080
#define AT_BYTES (BM * BKB)          // 16384
#define STAGE_BYTES (2 * AT_BYTES)   // 32768
#define SMEM_REQ (NST * STAGE_BYTES) // 65536 -> 2 CTAs/SM

#define NQ 128                       // quantizer CTAs (<=148: resident even at 1 CTA/SM)
#define ROWS_PER_Q (NB / NQ)         // 64
#define QPB 2                        // quantizer CTAs per 128-row block

// ---- scratch (static device globals; no allocations allowed) ----
__device__ uint32_t           g_q8[(size_t)NB * ND / 4];    // s8 normalized x512 (8 MB)
__device__ float              g_inv[NB];                    // 1/max(norm, eps)
__device__ unsigned long long g_cand[NB][NTB];              // per-(row, colblock) winner
__device__ double             g_loss;
__device__ unsigned int       g_done;
__device__ volatile int       g_flag[NTB];                  // block-ready flags (zero-init)
__device__ int                g_cnt[NTB];                   // quantizer completion counters

// monotonic s32 -> u32 key (order-preserving)
__device__ __forceinline__ unsigned int ikey(int s) {
    return (unsigned int)s ^ 0x80000000u;
}

// ---------------------------------------------------------------------------
// K1 helpers
// ---------------------------------------------------------------------------
__device__ __forceinline__ void ldm_x4(uint32_t (&r)[4], uint32_t addr) {
    asm volatile("ldmatrix.sync.aligned.m8n8.x4.shared.b16 {%0,%1,%2,%3}, [%4];"
                 : "=r"(r[0]), "=r"(r[1]), "=r"(r[2]), "=r"(r[3]) : "r"(addr));
}

__device__ __forceinline__ void imma16832(int (&d)[4], const uint32_t (&a)[4],
                                          uint32_t b0, uint32_t b1) {
    asm volatile(
        "mma.sync.aligned.m16n8k32.row.col.s32.s8.s8.s32 "
        "{%0,%1,%2,%3}, {%4,%5,%6,%7}, {%8,%9}, {%0,%1,%2,%3};"
        : "+r"(d[0]), "+r"(d[1]), "+r"(d[2]), "+r"(d[3])
        : "r"(a[0]), "r"(a[1]), "r"(a[2]), "r"(a[3]), "r"(b0), "r"(b1));
}

__device__ __forceinline__ void load_chunk(uint32_t base, int blkRow, int blkCol,
                                           int tid, int c) {
    const int k0 = c * BKB;
    const uint32_t stage = base + (uint32_t)(c % NST) * STAGE_BYTES;
    const uint8_t* q8 = reinterpret_cast<const uint8_t*>(g_q8);
    #pragma unroll
    for (int i = 0; i < 8; i++) {
        int idx  = i * 256 + tid;        // 0..2047 ; first 1024 = A, rest = B
        int isB  = idx >> 10;
        int lidx = idx & 1023;
        int row  = lidx >> 3;            // 0..127
        int ch   = lidx & 7;             // 16B chunk within 128B row
        const uint8_t* src =
            q8 + (size_t)((isB ? blkCol : blkRow) + row) * ND + k0 + ch * 16;
        uint32_t dst = stage + (uint32_t)isB * AT_BYTES +
                       (uint32_t)(row * 128 + ((ch ^ (row & 7)) * 16));
        asm volatile("cp.async.cg.shared.global [%0], [%1], 16;"
                     :: "r"(dst), "l"(src));
    }
    asm volatile("cp.async.commit_group;" ::: "memory");
}

// ---------------------------------------------------------------------------
// K1: fused quantize + int8 GEMM tiles + dual-sided block-winner epilogue.
// ---------------------------------------------------------------------------
__global__ __launch_bounds__(256, 2) void dot_argmax_mma(const float* __restrict__ x) {
    extern __shared__ __align__(1024) char dynsm[];
    const int tid  = threadIdx.x;
    const int wid  = tid >> 5;
    const int lane = tid & 31;
    const int wm   = wid & 1;        // 2 M-blocks of 64
    const int wn   = wid >> 1;       // 4 N-blocks of 32
    const int L    = blockIdx.x;

    if (L == 0 && tid == 0) { g_loss = 0.0; g_done = 0u; }

    // ---- phase 0: quantization by the first NQ CTAs (warp-per-row) ----
    if (L < NQ) {
        #pragma unroll 1
        for (int r = 0; r < ROWS_PER_Q / 8; r++) {
            const int row = L * ROWS_PER_Q + wid * (ROWS_PER_Q / 8) + r;
            const float4* xr4 = reinterpret_cast<const float4*>(x + (size_t)row * ND);
            float4 v[8];
            float s = 0.f;
            #pragma unroll
            for (int i = 0; i < 8; i++) {
                v[i] = xr4[i * 32 + lane];
                s = fmaf(v[i].x, v[i].x, s);
                s = fmaf(v[i].y, v[i].y, s);
                s = fmaf(v[i].z, v[i].z, s);
                s = fmaf(v[i].w, v[i].w, s);
            }
            #pragma unroll
            for (int o = 16; o; o >>= 1) s += __shfl_xor_sync(0xffffffffu, s, o);

            const float inv = 1.f / fmaxf(sqrtf(s), EPSF);
            if (lane == 0) g_inv[row] = inv;

            const float qs = inv * QSCALE;
            uint32_t* q8row = g_q8 + (size_t)row * 256;
            #pragma unroll
            for (int i = 0; i < 8; i++) {
                int q0 = max(-127, min(127, __float2int_rn(v[i].x * qs)));
                int q1 = max(-127, min(127, __float2int_rn(v[i].y * qs)));
                int q2 = max(-127, min(127, __float2int_rn(v[i].z * qs)));
                int q3 = max(-127, min(127, __float2int_rn(v[i].w * qs)));
                q8row[i * 32 + lane] =
                    (uint32_t)(q0 & 0xff) | ((uint32_t)(q1 & 0xff) << 8) |
                    ((uint32_t)(q2 & 0xff) << 16) | ((uint32_t)(q3 & 0xff) << 24);
            }
        }
        __syncthreads();
        if (tid == 0) {
            __threadfence();                       // publish rows
            const int b = L / QPB;
            if (atomicAdd(&g_cnt[b], 1) == QPB - 1) {
                __threadfence();
                atomicExch((int*)&g_flag[b], 1);   // release block b
            }
        }
    }

    // ---- tile mapping: linear index -> upper-triangular (bi, bj), bi <= bj
    int bi = (int)floorf((2.f * NTB + 1.f -
                          sqrtf((2.f * NTB + 1.f) * (2.f * NTB + 1.f) - 8.f * L)) * 0.5f);
    if (bi < 0) bi = 0;
    while (bi + 1 <= NTB - 1 && (bi + 1) * NTB - ((bi + 1) * bi) / 2 <= L) bi++;
    while (bi > 0 && bi * NTB - (bi * (bi - 1)) / 2 > L) bi--;
    const int bj = bi + (L - (bi * NTB - (bi * (bi - 1)) / 2));
    const int blkRow = bi * BM;
    const int blkCol = bj * BN;

    // ---- wait for both source blocks to be quantized ----
    if (tid == 0) {
        while (g_flag[bi] == 0) __nanosleep(128);
        while (g_flag[bj] == 0) __nanosleep(128);
    }
    __syncthreads();
    __threadfence();   // per-thread acquire of published q8 data

    uint32_t sbase = (uint32_t)__cvta_generic_to_shared(dynsm);

    int acc[4][4][4];
    #pragma unroll
    for (int i = 0; i < 4; i++)
        #pragma unroll
        for (int j = 0; j < 4; j++)
            #pragma unroll
            for (int q = 0; q < 4; q++) acc[i][j][q] = 0;

    const int lrow = lane & 15;
    const int chl  = lane >> 4;
    int aRow[4], bRow[2];
    #pragma unroll
    for (int i = 0; i < 4; i++) aRow[i] = wm * 64 + i * 16 + lrow;
    #pragma unroll
    for (int nb = 0; nb < 2; nb++) bRow[nb] = wn * 32 + nb * 16 + lrow;

    // prologue: fill both stages
    load_chunk(sbase, blkRow, blkCol, tid, 0);
    load_chunk(sbase, blkRow, blkCol, tid, 1);

    for (int c = 0; c < NCH; c++) {
        if (c + 1 < NCH) asm volatile("cp.async.wait_group 1;" ::: "memory");
        else             asm volatile("cp.async.wait_group 0;" ::: "memory");
        __syncthreads();

        const uint32_t stA = sbase + (uint32_t)(c % NST) * STAGE_BYTES;
        const uint32_t stB = stA + AT_BYTES;

        #pragma unroll
        for (int kk = 0; kk < 4; kk++) {   // 4 k32 steps inside 128B chunk
            const int cb = kk * 2 + chl;
            uint32_t aF[4][4];
            #pragma unroll
            for (int i = 0; i < 4; i++) {
                uint32_t ad = stA + (uint32_t)(aRow[i] * 128 +
                                               ((cb ^ (aRow[i] & 7)) * 16));
                ldm_x4(aF[i], ad);
            }
            uint32_t bF[2][4];
            #pragma unroll
            for (int nb = 0; nb < 2; nb++) {
                uint32_t bd = stB + (uint32_t)(bRow[nb] * 128 +
                                               ((cb ^ (bRow[nb] & 7)) * 16));
                ldm_x4(bF[nb], bd);
            }
            #pragma unroll
            for (int i = 0; i < 4; i++) {
                imma16832(acc[i][0], aF[i], bF[0][0], bF[0][2]);
                imma16832(acc[i][1], aF[i], bF[0][1], bF[0][3]);
                imma16832(acc[i][2], aF[i], bF[1][0], bF[1][2]);
                imma16832(acc[i][3], aF[i], bF[1][1], bF[1][3]);
            }
        }

        __syncthreads();                   // stage (c%2) fully consumed
        if (c + 2 < NCH) load_chunk(sbase, blkRow, blkCol, tid, c + 2);
    }

    // ---- epilogue: dual-sided block winners ----
    unsigned long long* sB = reinterpret_cast<unsigned long long*>(dynsm);
    sB[tid] = 0ull;   // [0,128)=row side, [128,256)=col side
    __syncthreads();

    const int qr = lane >> 2;
    const int qc = (lane & 3) * 2;

    // row side: thread's 8 rows, reduce over its 8 cols
    #pragma unroll
    for (int i = 0; i < 4; i++) {
        #pragma unroll
        for (int h = 0; h < 2; h++) {
            const int lr = wm * 64 + i * 16 + h * 8 + qr;
            const int gr = blkRow + lr;
            unsigned long long best = 0ull;
            #pragma unroll
            for (int j = 0; j < 4; j++) {
                #pragma unroll
                for (int e = 0; e < 2; e++) {
                    const int gc = blkCol + wn * 32 + j * 8 + qc + e;
                    unsigned long long key =
                        ((unsigned long long)ikey(acc[i][j][h * 2 + e]) << 32) |
                        (unsigned int)gc;
                    if (gc != gr && key > best) best = key;
                }
            }
            #pragma unroll
            for (int o = 1; o < 4; o <<= 1) {
                unsigned long long other = __shfl_xor_sync(0xffffffffu, best, o);
                if (other > best) best = other;
            }
            if ((lane & 3) == 0) atomicMax(&sB[lr], best);
        }
    }

    // col side (symmetry): thread's 8 cols, reduce over its 8 rows
    #pragma unroll
    for (int j = 0; j < 4; j++) {
        #pragma unroll
        for (int e = 0; e < 2; e++) {
            const int lc = wn * 32 + j * 8 + qc + e;
            const int gc = blkCol + lc;
            unsigned long long best = 0ull;
            #pragma unroll
            for (int i = 0; i < 4; i++) {
                #pragma unroll
                for (int h = 0; h < 2; h++) {
                    const int gr = blkRow + wm * 64 + i * 16 + h * 8 + qr;
                    unsigned long long key =
                        ((unsigned long long)ikey(acc[i][j][h * 2 + e]) << 32) |
                        (unsigned int)gr;
                    if (gr != gc && key > best) best = key;
                }
            }
            #pragma unroll
            for (int o = 4; o < 32; o <<= 1) {
                unsigned long long other = __shfl_xor_sync(0xffffffffu, best, o);
                if (other > best) best = other;
            }
            if (lane < 4) atomicMax(&sB[128 + lc], best);
        }
    }

    __syncthreads();
    // every (row, colblock) cell is owned by exactly one tile -> plain stores
    if (tid < 128) {
        g_cand[blkRow + tid][bj] = sB[tid];
    } else if (bi != bj) {   // diagonal: col side duplicates row side; skip
        g_cand[blkCol + (tid - 128)][bi] = sB[tid];
    }
}

// ---------------------------------------------------------------------------
// K2: per-row top-2 of block winners -> fp32 rescore (on-the-fly normalize);
//     log -> g_loss; last block writes the output and clears flags.
// ---------------------------------------------------------------------------
__global__ __launch_bounds__(128) void rescore_kernel(const float* __restrict__ x,
                                                      float* __restrict__ out) {
    const int row  = blockIdx.x;
    const int tid  = threadIdx.x;
    const int lane = tid & 31;
    const int wid  = tid >> 5;

    __shared__ unsigned long long cnd[NTB];
    __shared__ unsigned long long wred[4];
    __shared__ unsigned long long m1s, m2s;

    if (tid < NTB) cnd[tid] = g_cand[row][tid];
    __syncthreads();

    // pass 1: max key
    unsigned long long k = (tid < NTB) ? cnd[tid] : 0ull;
    unsigned long long t = k;
    #pragma unroll
    for (int o = 16; o; o >>= 1) {
        unsigned long long v = __shfl_xor_sync(0xffffffffu, t, o);
        if (v > t) t = v;
    }
    if (lane == 0) wred[wid] = t;
    __syncthreads();
    if (tid == 0) {
        unsigned long long m = wred[0];
        if (wred[1] > m) m = wred[1];
        if (wred[2] > m) m = wred[2];
        if (wred[3] > m) m = wred[3];
        m1s = m;
    }
    __syncthreads();
    const unsigned long long m1 = m1s;

    // pass 2: max key excluding m1 (keys unique: distinct col blocks)
    t = (k != m1) ? k : 0ull;
    #pragma unroll
    for (int o = 16; o; o >>= 1) {
        unsigned long long v = __shfl_xor_sync(0xffffffffu, t, o);
        if (v > t) t = v;
    }
    if (lane == 0) wred[wid] = t;
    __syncthreads();
    if (tid == 0) {
        unsigned long long m = wred[0];
        if (wred[1] > m) m = wred[1];
        if (wred[2] > m) m = wred[2];
        if (wred[3] > m) m = wred[3];
        m2s = m;
    }
    __syncthreads();

    const int c1 = (int)(unsigned int)(m1 & 0xffffffffull);
    const int c2 = (int)(unsigned int)(m2s & 0xffffffffull);

    // fp32 rescore: normalize on the fly (a_i*inv_a == stored xn numerics)
    const float ia = g_inv[row];
    const float i1 = g_inv[c1];
    const float i2 = g_inv[c2];
    const float4* A  = reinterpret_cast<const float4*>(x + (size_t)row * ND);
    const float4* B1 = reinterpret_cast<const float4*>(x + (size_t)c1 * ND);
    const float4* B2 = reinterpret_cast<const float4*>(x + (size_t)c2 * ND);

    float d1 = 0.f, d2 = 0.f, s1 = 0.f, s2 = 0.f;
    #pragma unroll
    for (int i = 0; i < 2; i++) {
        int idx = i * 128 + tid;
        float4 av = A[idx], b1v = B1[idx], b2v = B2[idx];
        float ax = av.x * ia, ay = av.y * ia, az = av.z * ia, aw = av.w * ia;
        float px = b1v.x * i1, py = b1v.y * i1, pz = b1v.z * i1, pw = b1v.w * i1;
        float qx = b2v.x * i2, qy = b2v.y * i2, qz = b2v.z * i2, qw = b2v.w * i2;
        d1 = fmaf(ax, px, d1); d1 = fmaf(ay, py, d1);
        d1 = fmaf(az, pz, d1); d1 = fmaf(aw, pw, d1);
        d2 = fmaf(ax, qx, d2); d2 = fmaf(ay, qy, d2);
        d2 = fmaf(az, qz, d2); d2 = fmaf(aw, qw, d2);
        float e;
        e = ax - px + EPSF; s1 = fmaf(e, e, s1);
        e = ay - py + EPSF; s1 = fmaf(e, e, s1);
        e = az - pz + EPSF; s1 = fmaf(e, e, s1);
        e = aw - pw + EPSF; s1 = fmaf(e, e, s1);
        e = ax - qx + EPSF; s2 = fmaf(e, e, s2);
        e = ay - qy + EPSF; s2 = fmaf(e, e, s2);
        e = az - qz + EPSF; s2 = fmaf(e, e, s2);
        e = aw - qw + EPSF; s2 = fmaf(e, e, s2);
    }
    #pragma unroll
    for (int o = 16; o; o >>= 1) {
        d1 += __shfl_xor_sync(0xffffffffu, d1, o);
        d2 += __shfl_xor_sync(0xffffffffu, d2, o);
        s1 += __shfl_xor_sync(0xffffffffu, s1, o);
        s2 += __shfl_xor_sync(0xffffffffu, s2, o);
    }
    __shared__ float fr[4][4];
    if (lane == 0) { fr[wid][0] = d1; fr[wid][1] = d2; fr[wid][2] = s1; fr[wid][3] = s2; }
    __syncthreads();
    if (tid == 0) {
        float D1 = fr[0][0] + fr[1][0] + fr[2][0] + fr[3][0];
        float D2 = fr[0][1] + fr[1][1] + fr[2][1] + fr[3][1];
        float S1 = fr[0][2] + fr[1][2] + fr[2][2] + fr[3][2];
        float S2 = fr[0][3] + fr[1][3] + fr[2][3] + fr[3][3];
        bool take2 = (D2 > D1) || (D2 == D1 && c2 < c1);  // argmax first-index tiebreak
        float S = take2 ? S2 : S1;
        atomicAdd(&g_loss, (double)logf(sqrtf(S) + EPSF));
        __threadfence();
        unsigned int done = atomicAdd(&g_done, 1u);
        if (done == NB - 1) {
            out[0] = (float)(-g_loss / (double)NB);
            // clear readiness state for the next graph replay
            for (int b = 0; b < NTB; b++) { g_flag[b] = 0; g_cnt[b] = 0; }
        }
    }
}

extern "C" void kernel_launch(void* const* d_in, const int* in_sizes, int n_in,
                              void* d_out, int out_size) {
    const float* x = (const float*)d_in[0];
    float* out = (float*)d_out;

    cudaFuncSetAttribute(dot_argmax_mma,
                         cudaFuncAttributeMaxDynamicSharedMemorySize, SMEM_REQ);

    dot_argmax_mma<<<NTRI, 256, SMEM_REQ>>>(x);
    rescore_kernel<<<NB, 128>>>(x, out);
}

// round 12
// speedup vs baseline: 1.0170x; 1.0170x over previous
#include <cuda_runtime.h>
#include <math.h>
#include <stdint.h>

// KoLeoLoss: x [8192, 1024] fp32 -> scalar loss
//   xn = x / max(||x||, 1e-8)
//   I[r] = argmax_{c != r} (xn[r] . xn[c])
//   dist[r] = || xn[r] - xn[I[r]] + 1e-8 ||_2
//   loss = -mean(log(dist + 1e-8))
//
// Pipeline (3 launches):
//   K1: warp-per-row norms + s8 quantized copy (x512); resets g_loss/g_done
//   K2: int8 mma.m16n8k32 (IMMA, 1024 MAC/cyc/SM) on upper-triangular
//       128x128 tiles; 2-stage ring, 2 CTAs/SM; dual-sided reduction ->
//       per-(row, col-block) winners (plain stores)
//   K3: warp-per-row top-2 of 64 block winners (shfl butterflies, no smem);
//       fp32 rescore of both (on-the-fly normalize) -> log -> g_loss;
//       last row writes the output scalar (fused finalize)

#define NB 8192
#define ND 1024
#define EPSF 1e-8f
#define QSCALE 512.0f

#define BM 128
#define BN 128
#define BKB 128                      // K-bytes per chunk (128 s8)
#define NCH (ND / BKB)               // 8
#define NST 2
#define NTB (NB / BM)                // 64
#define NTRI (NTB * (NTB + 1) / 2)   // 2080
#define AT_BYTES (BM * BKB)          // 16384
#define STAGE_BYTES (2 * AT_BYTES)   // 32768
#define SMEM_REQ (NST * STAGE_BYTES) // 65536 -> 2 CTAs/SM

// ---- scratch (static device globals; no allocations allowed) ----
__device__ uint32_t           g_q8[(size_t)NB * ND / 4];    // s8 normalized x512 (8 MB)
__device__ float              g_inv[NB];                    // 1/max(norm, eps)
__device__ unsigned long long g_cand[NB][NTB];              // per-(row, colblock) winner
__device__ double             g_loss;
__device__ unsigned int       g_done;

// monotonic s32 -> u32 key (order-preserving)
__device__ __forceinline__ unsigned int ikey(int s) {
    return (unsigned int)s ^ 0x80000000u;
}

// ---------------------------------------------------------------------------
// K1: warp-per-row norms + s8 quantization. 8 warps/block, 1024 blocks.
// ---------------------------------------------------------------------------
__global__ __launch_bounds__(256) void normalize_kernel(const float* __restrict__ x) {
    const int lane = threadIdx.x & 31;
    const int wrp  = threadIdx.x >> 5;
    const int row  = blockIdx.x * 8 + wrp;
    if (blockIdx.x == 0 && threadIdx.x == 0) { g_loss = 0.0; g_done = 0u; }

    const float4* xr4 = reinterpret_cast<const float4*>(x + (size_t)row * ND);
    float4 v[8];
    float s = 0.f;
    #pragma unroll
    for (int i = 0; i < 8; i++) {
        v[i] = xr4[i * 32 + lane];
        s = fmaf(v[i].x, v[i].x, s);
        s = fmaf(v[i].y, v[i].y, s);
        s = fmaf(v[i].z, v[i].z, s);
        s = fmaf(v[i].w, v[i].w, s);
    }
    #pragma unroll
    for (int o = 16; o; o >>= 1) s += __shfl_xor_sync(0xffffffffu, s, o);

    const float inv = 1.f / fmaxf(sqrtf(s), EPSF);
    if (lane == 0) g_inv[row] = inv;

    const float qs = inv * QSCALE;
    uint32_t* q8row = g_q8 + (size_t)row * 256;
    #pragma unroll
    for (int i = 0; i < 8; i++) {
        int q0 = max(-127, min(127, __float2int_rn(v[i].x * qs)));
        int q1 = max(-127, min(127, __float2int_rn(v[i].y * qs)));
        int q2 = max(-127, min(127, __float2int_rn(v[i].z * qs)));
        int q3 = max(-127, min(127, __float2int_rn(v[i].w * qs)));
        q8row[i * 32 + lane] =
            (uint32_t)(q0 & 0xff) | ((uint32_t)(q1 & 0xff) << 8) |
            ((uint32_t)(q2 & 0xff) << 16) | ((uint32_t)(q3 & 0xff) << 24);
    }
}

// ---------------------------------------------------------------------------
// K2: int8 GEMM tiles + dual-sided block-winner epilogue.
// ---------------------------------------------------------------------------
__device__ __forceinline__ void ldm_x4(uint32_t (&r)[4], uint32_t addr) {
    asm volatile("ldmatrix.sync.aligned.m8n8.x4.shared.b16 {%0,%1,%2,%3}, [%4];"
                 : "=r"(r[0]), "=r"(r[1]), "=r"(r[2]), "=r"(r[3]) : "r"(addr));
}

__device__ __forceinline__ void imma16832(int (&d)[4], const uint32_t (&a)[4],
                                          uint32_t b0, uint32_t b1) {
    asm volatile(
        "mma.sync.aligned.m16n8k32.row.col.s32.s8.s8.s32 "
        "{%0,%1,%2,%3}, {%4,%5,%6,%7}, {%8,%9}, {%0,%1,%2,%3};"
        : "+r"(d[0]), "+r"(d[1]), "+r"(d[2]), "+r"(d[3])
        : "r"(a[0]), "r"(a[1]), "r"(a[2]), "r"(a[3]), "r"(b0), "r"(b1));
}

__device__ __forceinline__ void load_chunk(uint32_t base, int blkRow, int blkCol,
                                           int tid, int c) {
    const int k0 = c * BKB;
    const uint32_t stage = base + (uint32_t)(c % NST) * STAGE_BYTES;
    const uint8_t* q8 = reinterpret_cast<const uint8_t*>(g_q8);
    #pragma unroll
    for (int i = 0; i < 8; i++) {
        int idx  = i * 256 + tid;        // 0..2047 ; first 1024 = A, rest = B
        int isB  = idx >> 10;
        int lidx = idx & 1023;
        int row  = lidx >> 3;            // 0..127
        int ch   = lidx & 7;             // 16B chunk within 128B row
        const uint8_t* src =
            q8 + (size_t)((isB ? blkCol : blkRow) + row) * ND + k0 + ch * 16;
        uint32_t dst = stage + (uint32_t)isB * AT_BYTES +
                       (uint32_t)(row * 128 + ((ch ^ (row & 7)) * 16));
        asm volatile("cp.async.cg.shared.global [%0], [%1], 16;"
                     :: "r"(dst), "l"(src));
    }
    asm volatile("cp.async.commit_group;" ::: "memory");
}

__global__ __launch_bounds__(256, 2) void dot_argmax_mma() {
    extern __shared__ __align__(1024) char dynsm[];
    const int tid  = threadIdx.x;
    const int wid  = tid >> 5;
    const int lane = tid & 31;
    const int wm   = wid & 1;        // 2 M-blocks of 64
    const int wn   = wid >> 1;       // 4 N-blocks of 32

    // linear tile index -> upper-triangular (bi, bj), bi <= bj
    const int L = blockIdx.x;
    int bi = (int)floorf((2.f * NTB + 1.f -
                          sqrtf((2.f * NTB + 1.f) * (2.f * NTB + 1.f) - 8.f * L)) * 0.5f);
    if (bi < 0) bi = 0;
    while (bi + 1 <= NTB - 1 && (bi + 1) * NTB - ((bi + 1) * bi) / 2 <= L) bi++;
    while (bi > 0 && bi * NTB - (bi * (bi - 1)) / 2 > L) bi--;
    const int bj = bi + (L - (bi * NTB - (bi * (bi - 1)) / 2));
    const int blkRow = bi * BM;
    const int blkCol = bj * BN;

    uint32_t sbase = (uint32_t)__cvta_generic_to_shared(dynsm);

    int acc[4][4][4];
    #pragma unroll
    for (int i = 0; i < 4; i++)
        #pragma unroll
        for (int j = 0; j < 4; j++)
            #pragma unroll
            for (int q = 0; q < 4; q++) acc[i][j][q] = 0;

    const int lrow = lane & 15;
    const int chl  = lane >> 4;
    int aRow[4], bRow[2];
    #pragma unroll
    for (int i = 0; i < 4; i++) aRow[i] = wm * 64 + i * 16 + lrow;
    #pragma unroll
    for (int nb = 0; nb < 2; nb++) bRow[nb] = wn * 32 + nb * 16 + lrow;

    // prologue: fill both stages
    load_chunk(sbase, blkRow, blkCol, tid, 0);
    load_chunk(sbase, blkRow, blkCol, tid, 1);

    for (int c = 0; c < NCH; c++) {
        if (c + 1 < NCH) asm volatile("cp.async.wait_group 1;" ::: "memory");
        else             asm volatile("cp.async.wait_group 0;" ::: "memory");
        __syncthreads();

        const uint32_t stA = sbase + (uint32_t)(c % NST) * STAGE_BYTES;
        const uint32_t stB = stA + AT_BYTES;

        #pragma unroll
        for (int kk = 0; kk < 4; kk++) {   // 4 k32 steps inside 128B chunk
            const int cb = kk * 2 + chl;
            uint32_t aF[4][4];
            #pragma unroll
            for (int i = 0; i < 4; i++) {
                uint32_t ad = stA + (uint32_t)(aRow[i] * 128 +
                                               ((cb ^ (aRow[i] & 7)) * 16));
                ldm_x4(aF[i], ad);
            }
            uint32_t bF[2][4];
            #pragma unroll
            for (int nb = 0; nb < 2; nb++) {
                uint32_t bd = stB + (uint32_t)(bRow[nb] * 128 +
                                               ((cb ^ (bRow[nb] & 7)) * 16));
                ldm_x4(bF[nb], bd);
            }
            #pragma unroll
            for (int i = 0; i < 4; i++) {
                imma16832(acc[i][0], aF[i], bF[0][0], bF[0][2]);
                imma16832(acc[i][1], aF[i], bF[0][1], bF[0][3]);
                imma16832(acc[i][2], aF[i], bF[1][0], bF[1][2]);
                imma16832(acc[i][3], aF[i], bF[1][1], bF[1][3]);
            }
        }

        __syncthreads();                   // stage (c%2) fully consumed
        if (c + 2 < NCH) load_chunk(sbase, blkRow, blkCol, tid, c + 2);
    }

    // ---- epilogue: dual-sided block winners ----
    unsigned long long* sB = reinterpret_cast<unsigned long long*>(dynsm);
    sB[tid] = 0ull;   // [0,128)=row side, [128,256)=col side
    __syncthreads();

    const int qr = lane >> 2;
    const int qc = (lane & 3) * 2;

    // row side: thread's 8 rows, reduce over its 8 cols
    #pragma unroll
    for (int i = 0; i < 4; i++) {
        #pragma unroll
        for (int h = 0; h < 2; h++) {
            const int lr = wm * 64 + i * 16 + h * 8 + qr;
            const int gr = blkRow + lr;
            unsigned long long best = 0ull;
            #pragma unroll
            for (int j = 0; j < 4; j++) {
                #pragma unroll
                for (int e = 0; e < 2; e++) {
                    const int gc = blkCol + wn * 32 + j * 8 + qc + e;
                    unsigned long long key =
                        ((unsigned long long)ikey(acc[i][j][h * 2 + e]) << 32) |
                        (unsigned int)gc;
                    if (gc != gr && key > best) best = key;
                }
            }
            #pragma unroll
            for (int o = 1; o < 4; o <<= 1) {
                unsigned long long other = __shfl_xor_sync(0xffffffffu, best, o);
                if (other > best) best = other;
            }
            if ((lane & 3) == 0) atomicMax(&sB[lr], best);
        }
    }

    // col side (symmetry): thread's 8 cols, reduce over its 8 rows
    #pragma unroll
    for (int j = 0; j < 4; j++) {
        #pragma unroll
        for (int e = 0; e < 2; e++) {
            const int lc = wn * 32 + j * 8 + qc + e;
            const int gc = blkCol + lc;
            unsigned long long best = 0ull;
            #pragma unroll
            for (int i = 0; i < 4; i++) {
                #pragma unroll
                for (int h = 0; h < 2; h++) {
                    const int gr = blkRow + wm * 64 + i * 16 + h * 8 + qr;
                    unsigned long long key =
                        ((unsigned long long)ikey(acc[i][j][h * 2 + e]) << 32) |
                        (unsigned int)gr;
                    if (gr != gc && key > best) best = key;
                }
            }
            #pragma unroll
            for (int o = 4; o < 32; o <<= 1) {
                unsigned long long other = __shfl_xor_sync(0xffffffffu, best, o);
                if (other > best) best = other;
            }
            if (lane < 4) atomicMax(&sB[128 + lc], best);
        }
    }

    __syncthreads();
    // every (row, colblock) cell is owned by exactly one tile -> plain stores
    if (tid < 128) {
        g_cand[blkRow + tid][bj] = sB[tid];
    } else if (bi != bj) {   // diagonal: col side duplicates row side; skip
        g_cand[blkCol + (tid - 128)][bi] = sB[tid];
    }
}

// ---------------------------------------------------------------------------
// K3: warp-per-row top-2 + fp32 rescore (no smem, no __syncthreads).
//     8 warps/block, 1024 blocks. Last finished row writes the output.
// ---------------------------------------------------------------------------
__global__ __launch_bounds__(256) void rescore_kernel(const float* __restrict__ x,
                                                      float* __restrict__ out) {
    const int lane = threadIdx.x & 31;
    const int wrp  = threadIdx.x >> 5;
    const int row  = blockIdx.x * 8 + wrp;

    // 64 candidates, 2 per lane
    const unsigned long long a = g_cand[row][lane];
    const unsigned long long b = g_cand[row][lane + 32];
    unsigned long long mx = a > b ? a : b;

    // top-1 via butterfly (all lanes end with the max)
    unsigned long long m1 = mx;
    #pragma unroll
    for (int o = 16; o; o >>= 1) {
        unsigned long long v = __shfl_xor_sync(0xffffffffu, m1, o);
        if (v > m1) m1 = v;
    }
    // top-2: exclude the unique m1 entry
    unsigned long long sec = (a == m1) ? b : ((b == m1) ? a : mx);
    unsigned long long m2 = sec;
    #pragma unroll
    for (int o = 16; o; o >>= 1) {
        unsigned long long v = __shfl_xor_sync(0xffffffffu, m2, o);
        if (v > m2) m2 = v;
    }

    const int c1 = (int)(unsigned int)(m1 & 0xffffffffull);
    const int c2 = (int)(unsigned int)(m2 & 0xffffffffull);

    // fp32 rescore: normalize on the fly (a_i*inv_a == stored xn numerics)
    const float ia = g_inv[row];
    const float i1 = g_inv[c1];
    const float i2 = g_inv[c2];
    const float4* A  = reinterpret_cast<const float4*>(x + (size_t)row * ND);
    const float4* B1 = reinterpret_cast<const float4*>(x + (size_t)c1 * ND);
    const float4* B2 = reinterpret_cast<const float4*>(x + (size_t)c2 * ND);

    float d1 = 0.f, d2 = 0.f, s1 = 0.f, s2 = 0.f;
    #pragma unroll
    for (int i = 0; i < 8; i++) {
        const int idx = i * 32 + lane;
        float4 av = A[idx], b1v = B1[idx], b2v = B2[idx];
        float ax = av.x * ia, ay = av.y * ia, az = av.z * ia, aw = av.w * ia;
        float px = b1v.x * i1, py = b1v.y * i1, pz = b1v.z * i1, pw = b1v.w * i1;
        float qx = b2v.x * i2, qy = b2v.y * i2, qz = b2v.z * i2, qw = b2v.w * i2;
        d1 = fmaf(ax, px, d1); d1 = fmaf(ay, py, d1);
        d1 = fmaf(az, pz, d1); d1 = fmaf(aw, pw, d1);
        d2 = fmaf(ax, qx, d2); d2 = fmaf(ay, qy, d2);
        d2 = fmaf(az, qz, d2); d2 = fmaf(aw, qw, d2);
        float e;
        e = ax - px + EPSF; s1 = fmaf(e, e, s1);
        e = ay - py + EPSF; s1 = fmaf(e, e, s1);
        e = az - pz + EPSF; s1 = fmaf(e, e, s1);
        e = aw - pw + EPSF; s1 = fmaf(e, e, s1);
        e = ax - qx + EPSF; s2 = fmaf(e, e, s2);
        e = ay - qy + EPSF; s2 = fmaf(e, e, s2);
        e = az - qz + EPSF; s2 = fmaf(e, e, s2);
        e = aw - qw + EPSF; s2 = fmaf(e, e, s2);
    }
    #pragma unroll
    for (int o = 16; o; o >>= 1) {
        d1 += __shfl_xor_sync(0xffffffffu, d1, o);
        d2 += __shfl_xor_sync(0xffffffffu, d2, o);
        s1 += __shfl_xor_sync(0xffffffffu, s1, o);
        s2 += __shfl_xor_sync(0xffffffffu, s2, o);
    }

    if (lane == 0) {
        bool take2 = (d2 > d1) || (d2 == d1 && c2 < c1);  // argmax first-index tiebreak
        float S = take2 ? s2 : s1;
        atomicAdd(&g_loss, (double)logf(sqrtf(S) + EPSF));
        __threadfence();
        unsigned int done = atomicAdd(&g_done, 1u);
        if (done == NB - 1) {
            out[0] = (float)(-g_loss / (double)NB);
        }
    }
}

extern "C" void kernel_launch(void* const* d_in, const int* in_sizes, int n_in,
                              void* d_out, int out_size) {
    const float* x = (const float*)d_in[0];
    float* out = (float*)d_out;

    cudaFuncSetAttribute(dot_argmax_mma,
                         cudaFuncAttributeMaxDynamicSharedMemorySize, SMEM_REQ);

    normalize_kernel<<<NB / 8, 256>>>(x);
    dot_argmax_mma<<<NTRI, 256, SMEM_REQ>>>();
    rescore_kernel<<<NB / 8, 256>>>(x, out);
}